// round 12
// baseline (speedup 1.0000x reference)
#include <cuda_runtime.h>
#include <cuda_bf16.h>
#include <cstdint>
#include <math.h>

// ---------------- problem constants ----------------
#define NROW   4096
#define FDIM   256
#define HH     8
#define UU     64
#define CC     512      // U*H
#define NCREAL 520      // CC + HH
#define NCP    576      // padded to 9 tiles of 64
#define KCAT   768      // K for GEMM1: [Xhi|Xlo|Xhi]
#define G2_PLANE ((size_t)NCP * NROW)

// ---------------- device scratch (no allocs) ----------------
__device__ char           gAq   [(size_t)NROW * NROW]; // s8 adjacency (exact 0/1)
__device__ char           gBq   [3 * G2_PLANE];        // 3 digit planes of Hw^T (q = d2*2^14 + d1*2^7 + d0)
__device__ __nv_bfloat16  gXcat [NROW * KCAT];         // [Xhi|Xlo|Xhi]
__device__ __nv_bfloat16  gWcat [NCP  * KCAT];         // row c: [Whi|Whi|Wlo]; rows 512..575 stay 0
__device__ float          g_h   [NROW * NCP];          // X@W (cols 512..575 = 0)
__device__ float          g_hw  [NROW * NCREAL];       // [w*h (512) | w (8)] fp32
__device__ float          g_out2[NROW * NCP];          // A@Hw (scaled fp32)
__device__ float          g_part[16 * NCREAL];
__device__ float          g_f   [NCP];                 // per-column quant scale  (2^21-1)/M
__device__ float          g_s   [NCP];                 // per-column dequant scale M/(2^21-1)

// ---------------- helpers ----------------
__device__ __forceinline__ uint32_t smem_to_u32(const void* p) {
    uint32_t a;
    asm("{ .reg .u64 t; cvta.to.shared.u64 t, %1; cvt.u32.u64 %0, t; }" : "=r"(a) : "l"(p));
    return a;
}

#define LDSM_X4(r, addr) \
    asm volatile("ldmatrix.sync.aligned.m8n8.x4.shared.b16 {%0,%1,%2,%3}, [%4];" \
        : "=r"((r)[0]), "=r"((r)[1]), "=r"((r)[2]), "=r"((r)[3]) : "r"(addr))

__device__ __forceinline__ void mma16816(float* d, const uint32_t* a,
                                         uint32_t b0, uint32_t b1) {
    asm volatile(
        "mma.sync.aligned.m16n8k16.row.col.f32.bf16.bf16.f32 "
        "{%0,%1,%2,%3}, {%4,%5,%6,%7}, {%8,%9}, {%0,%1,%2,%3};"
        : "+f"(d[0]), "+f"(d[1]), "+f"(d[2]), "+f"(d[3])
        : "r"(a[0]), "r"(a[1]), "r"(a[2]), "r"(a[3]), "r"(b0), "r"(b1));
}

__device__ __forceinline__ void mma16832s8(int* d, const uint32_t* a,
                                           uint32_t b0, uint32_t b1) {
    asm volatile(
        "mma.sync.aligned.m16n8k32.row.col.s32.s8.s8.s32 "
        "{%0,%1,%2,%3}, {%4,%5,%6,%7}, {%8,%9}, {%0,%1,%2,%3};"
        : "+r"(d[0]), "+r"(d[1]), "+r"(d[2]), "+r"(d[3])
        : "r"(a[0]), "r"(a[1]), "r"(a[2]), "r"(a[3]), "r"(b0), "r"(b1));
}

// ---------------------------------------------------------------------------
// GEMM1: C = A @ B0t^T (bf16, exact hi/lo via K-concat). Tile 128x64, BK=64,
// 256 threads (warp tile 32x32), 3-stage cp.async, XOR-16B swizzle. (proven)
// ---------------------------------------------------------------------------
#define G1_STAGE 24576
#define G1_OFFB  16384

__global__ __launch_bounds__(256, 2) void k_gemm1(
    const __nv_bfloat16* __restrict__ A, int lda,
    const __nv_bfloat16* __restrict__ B0, int ldb,
    float* __restrict__ C, int ldc, int T)
{
    extern __shared__ char smem[];
    const uint32_t sb = smem_to_u32(smem);
    const int tid = threadIdx.x, lane = tid & 31, wid = tid >> 5;
    const int warp_m = wid & 3, warp_n = wid >> 2;
    const int m0 = blockIdx.y * 128, n0 = blockIdx.x * 64;

    auto issue_stage = [&](int t) {
        const uint32_t so = sb + (t % 3) * G1_STAGE;
        const __nv_bfloat16* Ak = A + (size_t)m0 * lda + t * 64;
#pragma unroll
        for (int i = 0; i < 4; i++) {
            const int idx = tid + (i << 8), r = idx >> 3, c = idx & 7;
            const void* src = Ak + (size_t)r * lda + c * 8;
            const uint32_t dst = so + r * 128 + ((c ^ (r & 7)) << 4);
            asm volatile("cp.async.cg.shared.global [%0], [%1], 16;" :: "r"(dst), "l"(src));
        }
        const __nv_bfloat16* Bk = B0 + (size_t)n0 * ldb + t * 64;
#pragma unroll
        for (int i = 0; i < 2; i++) {
            const int idx = tid + (i << 8), r = idx >> 3, c = idx & 7;
            const void* src = Bk + (size_t)r * ldb + c * 8;
            const uint32_t dst = so + G1_OFFB + r * 128 + ((c ^ (r & 7)) << 4);
            asm volatile("cp.async.cg.shared.global [%0], [%1], 16;" :: "r"(dst), "l"(src));
        }
        asm volatile("cp.async.commit_group;" ::: "memory");
    };

    float acc[2][4][4];
#pragma unroll
    for (int i = 0; i < 2; i++)
#pragma unroll
        for (int n = 0; n < 4; n++)
#pragma unroll
            for (int q = 0; q < 4; q++) acc[i][n][q] = 0.f;

    issue_stage(0);
    issue_stage(1);

    const int rA = warp_m * 32 + (lane & 15);
    const int rB = warp_n * 32 + (lane & 15);
    const int h  = lane >> 4;
    const int xa = rA & 7, xb = rB & 7;

    for (int t = 0; t < T; ++t) {
        asm volatile("cp.async.wait_group 1;" ::: "memory");
        __syncthreads();
        const uint32_t so = sb + (t % 3) * G1_STAGE;
        const uint32_t aAddr0 = so + rA * 128;
        const uint32_t bAddr0 = so + G1_OFFB + rB * 128;

#pragma unroll
        for (int ks = 0; ks < 4; ++ks) {
            uint32_t a[2][4], b0[2][4];
            const int ch = (2 * ks + h);
#pragma unroll
            for (int i = 0; i < 2; ++i)
                LDSM_X4(a[i], aAddr0 + i * 2048 + ((ch ^ xa) << 4));
#pragma unroll
            for (int j = 0; j < 2; ++j)
                LDSM_X4(b0[j], bAddr0 + j * 2048 + ((ch ^ xb) << 4));
#pragma unroll
            for (int i = 0; i < 2; ++i)
#pragma unroll
                for (int n = 0; n < 4; ++n)
                    mma16816(acc[i][n], a[i], b0[n >> 1][n & 1], b0[n >> 1][(n & 1) + 2]);
        }
        if (t + 2 < T) issue_stage(t + 2);
    }

    const int gid = lane >> 2, tig = lane & 3;
#pragma unroll
    for (int i = 0; i < 2; ++i) {
        const int row = m0 + warp_m * 32 + i * 16 + gid;
#pragma unroll
        for (int n = 0; n < 4; ++n) {
            const int col = n0 + warp_n * 32 + n * 8 + tig * 2;
            float* Cp = C + (size_t)row * ldc + col;
            *(float2*)Cp = make_float2(acc[i][n][0], acc[i][n][1]);
            *(float2*)(Cp + (size_t)8 * ldc) = make_float2(acc[i][n][2], acc[i][n][3]);
        }
    }
}

// ---------------------------------------------------------------------------
// GEMM2 (int8): C = (A_s8 @ [d2|d1|d0]) recombined * s_c.
// Tile 128x64, BK=128 (s8 bytes), 512 threads (16 warps 8x2, warp tile 16x32),
// 3-stage cp.async (40KB/stage), int32 accumulate (exact), s8 mma K=32.
// ---------------------------------------------------------------------------
#define G2_STAGE 40960
#define G2_OFFB  16384

__global__ __launch_bounds__(512, 1) void k_gemm2(
    const char* __restrict__ A,
    const char* __restrict__ B,
    const float* __restrict__ S,
    float* __restrict__ C, int T)
{
    extern __shared__ char smem[];
    const uint32_t sb = smem_to_u32(smem);
    const int tid = threadIdx.x, lane = tid & 31, wid = tid >> 5;
    const int warp_m = wid & 7, warp_n = wid >> 3;
    const int m0 = blockIdx.y * 128, n0 = blockIdx.x * 64;

    auto issue_stage = [&](int t) {
        const uint32_t so = sb + (t % 3) * G2_STAGE;
        // A tile: 128 rows x 128 bytes
#pragma unroll
        for (int i = 0; i < 2; i++) {
            const int idx = tid + (i << 9), r = idx >> 3, c = idx & 7;
            const void* src = A + (size_t)(m0 + r) * NROW + t * 128 + c * 16;
            const uint32_t dst = so + r * 128 + ((c ^ (r & 7)) << 4);
            asm volatile("cp.async.cg.shared.global [%0], [%1], 16;" :: "r"(dst), "l"(src));
        }
        // B: 3 digit planes, 64 rows x 128 bytes each
#pragma unroll
        for (int p = 0; p < 3; p++) {
            const int r = tid >> 3, c = tid & 7;
            const void* src = B + (size_t)p * G2_PLANE + (size_t)(n0 + r) * NROW + t * 128 + c * 16;
            const uint32_t dst = so + G2_OFFB + p * 8192 + r * 128 + ((c ^ (r & 7)) << 4);
            asm volatile("cp.async.cg.shared.global [%0], [%1], 16;" :: "r"(dst), "l"(src));
        }
        asm volatile("cp.async.commit_group;" ::: "memory");
    };

    int acc[3][4][4];
#pragma unroll
    for (int p = 0; p < 3; p++)
#pragma unroll
        for (int n = 0; n < 4; n++)
#pragma unroll
            for (int q = 0; q < 4; q++) acc[p][n][q] = 0;

    issue_stage(0);
    issue_stage(1);

    const int rA = warp_m * 16 + (lane & 15);
    const int rB = warp_n * 32 + (lane & 15);
    const int h  = lane >> 4;
    const int xa = rA & 7, xb = rB & 7;

    for (int t = 0; t < T; ++t) {
        asm volatile("cp.async.wait_group 1;" ::: "memory");
        __syncthreads();
        const uint32_t so = sb + (t % 3) * G2_STAGE;
        const uint32_t aAddr = so + rA * 128;
        const uint32_t bAddr = so + G2_OFFB + rB * 128;

#pragma unroll
        for (int ks = 0; ks < 4; ++ks) {
            const int ch = 2 * ks + h;
            uint32_t a[4];
            LDSM_X4(a, aAddr + ((ch ^ xa) << 4));
#pragma unroll
            for (int p = 0; p < 3; ++p) {
                uint32_t b[8];
                LDSM_X4(b,     bAddr + p * 8192 + ((ch ^ xb) << 4));
                LDSM_X4(b + 4, bAddr + p * 8192 + 2048 + ((ch ^ xb) << 4));
#pragma unroll
                for (int n = 0; n < 4; ++n) {
                    const int base = (n >> 1) * 4;
                    mma16832s8(acc[p][n], a, b[base + (n & 1)], b[base + (n & 1) + 2]);
                }
            }
        }
        if (t + 2 < T) issue_stage(t + 2);
    }

    // epilogue: recombine digits exactly (int64), scale (double), store fp32
    const int gid = lane >> 2, tig = lane & 3;
    const int row = m0 + warp_m * 16 + gid;
#pragma unroll
    for (int n = 0; n < 4; ++n) {
        const int col = n0 + warp_n * 32 + n * 8 + tig * 2;
        const double s0 = S[col], s1 = S[col + 1];
        long long v0 = (((long long)acc[0][n][0]) << 14) + (((long long)acc[1][n][0]) << 7) + acc[2][n][0];
        long long v1 = (((long long)acc[0][n][1]) << 14) + (((long long)acc[1][n][1]) << 7) + acc[2][n][1];
        long long v2 = (((long long)acc[0][n][2]) << 14) + (((long long)acc[1][n][2]) << 7) + acc[2][n][2];
        long long v3 = (((long long)acc[0][n][3]) << 14) + (((long long)acc[1][n][3]) << 7) + acc[2][n][3];
        C[(size_t)row * NCP + col]           = (float)((double)v0 * s0);
        C[(size_t)row * NCP + col + 1]       = (float)((double)v1 * s1);
        C[(size_t)(row + 8) * NCP + col]     = (float)((double)v2 * s0);
        C[(size_t)(row + 8) * NCP + col + 1] = (float)((double)v3 * s1);
    }
}

// ---------------- small prep kernels ----------------
__global__ __launch_bounds__(256) void k_convA(const float* __restrict__ A)
{
    const size_t idx = (size_t)blockIdx.x * 256 + threadIdx.x;   // 16 elems each
    const float4* src = (const float4*)A + idx * 4;
    char o[16];
#pragma unroll
    for (int v = 0; v < 4; ++v) {
        float4 f = src[v];
        o[v * 4 + 0] = f.x > 0.5f;
        o[v * 4 + 1] = f.y > 0.5f;
        o[v * 4 + 2] = f.z > 0.5f;
        o[v * 4 + 3] = f.w > 0.5f;
    }
    ((uint4*)gAq)[idx] = *(uint4*)o;
}

__global__ __launch_bounds__(256) void k_prepX(const float* __restrict__ X)
{
    const int idx = blockIdx.x * 256 + threadIdx.x;   // 1M
    const int i = idx >> 8, k = idx & 255;
    const float v = X[idx];
    __nv_bfloat16 hi = __float2bfloat16_rn(v);
    __nv_bfloat16 lo = __float2bfloat16_rn(v - __bfloat162float(hi));
    gXcat[i * KCAT + k]       = hi;
    gXcat[i * KCAT + 256 + k] = lo;
    gXcat[i * KCAT + 512 + k] = hi;
}

__global__ __launch_bounds__(256) void k_prepW(const float* __restrict__ W)
{
    const int idx = blockIdx.x * 256 + threadIdx.x;   // 131072
    const int k = idx >> 9, c = idx & 511;
    const float v = W[idx];
    __nv_bfloat16 hi = __float2bfloat16_rn(v);
    __nv_bfloat16 lo = __float2bfloat16_rn(v - __bfloat162float(hi));
    gWcat[c * KCAT + k]       = hi;
    gWcat[c * KCAT + 256 + k] = hi;
    gWcat[c * KCAT + 512 + k] = lo;
}

// w = exp(h . a_dst); write [w*h | w] row-major fp32
__global__ __launch_bounds__(256) void k_edst(const float* __restrict__ avec)
{
    const int j = blockIdx.x, warp = threadIdx.x >> 5, lane = threadIdx.x & 31;
    const float* hrow = g_h + (size_t)j * NCP + warp * UU;
    const float h0 = hrow[lane], h1 = hrow[lane + 32];
    float p = h0 * avec[UU + lane] + h1 * avec[UU + 32 + lane];
#pragma unroll
    for (int o = 16; o > 0; o >>= 1) p += __shfl_xor_sync(0xffffffffu, p, o);
    const float wv = expf(p);
    float* dst = g_hw + (size_t)j * NCREAL + warp * UU;
    dst[lane]      = wv * h0;
    dst[lane + 32] = wv * h1;
    if (lane == 0) g_hw[(size_t)j * NCREAL + CC + warp] = wv;
}

// per-column absmax of g_hw (two-stage, deterministic, coalesced)
__global__ __launch_bounds__(256) void k_colmax1()
{
    const int b = blockIdx.x, tid = threadIdx.x;
    const int j0 = b * 256;
    for (int c = tid; c < NCREAL; c += 256) {
        float m = 0.f;
        for (int j = 0; j < 256; ++j)
            m = fmaxf(m, fabsf(g_hw[(size_t)(j0 + j) * NCREAL + c]));
        g_part[b * NCREAL + c] = m;
    }
}

__global__ __launch_bounds__(576) void k_colmax2()
{
    const int c = threadIdx.x;   // 0..575
    float m = 0.f;
    if (c < NCREAL)
#pragma unroll
        for (int b = 0; b < 16; ++b) m = fmaxf(m, g_part[b * NCREAL + c]);
    g_f[c] = (m > 0.f) ? 2097151.0f / m : 0.f;
    g_s[c] = m / 2097151.0f;
}

// transpose + quantize g_hw[4096,520] -> 3 s8 digit planes [576,4096]
__global__ __launch_bounds__(256) void k_trans()
{
    __shared__ float tile[32][33];
    const int c0 = blockIdx.x * 32, j0 = blockIdx.y * 32;
    const int tid = threadIdx.x;
#pragma unroll
    for (int ph = 0; ph < 4; ++ph) {
        int idx = ph * 256 + tid, jr = idx >> 5, cc = idx & 31;
        int c = c0 + cc;
        tile[jr][cc] = (c < NCREAL) ? g_hw[(size_t)(j0 + jr) * NCREAL + c] : 0.f;
    }
    __syncthreads();
#pragma unroll
    for (int ph = 0; ph < 4; ++ph) {
        int idx = ph * 256 + tid, cr = idx >> 5, jc = idx & 31;
        const int c = c0 + cr, j = j0 + jc;
        const float f = g_f[c];
        const int q = lrintf(tile[jc][cr] * f);
        const int d2 = q >> 14;
        const int r  = q - (d2 << 14);
        gBq[(size_t)c * NROW + j]                = (char)d2;
        gBq[G2_PLANE + (size_t)c * NROW + j]     = (char)(r >> 7);
        gBq[2 * G2_PLANE + (size_t)c * NROW + j] = (char)(r & 127);
    }
}

// out[i, u*8+h] = relu( num/den ); fully-masked-row fallback computed on demand
__global__ __launch_bounds__(256) void k_epilogue(float* __restrict__ out)
{
    const int idx = blockIdx.x * 256 + threadIdx.x;
    const int i = idx >> 9, o = idx & 511;
    const int head = o & 7, u = o >> 3;
    const int col = head * UU + u;
    const float den = g_out2[(size_t)i * NCP + CC + head];
    float v;
    if (den > 0.f) {
        v = g_out2[(size_t)i * NCP + col] / den;
    } else {
        // reference softmax over an all-masked row degenerates to uniform 1/N
        float s = 0.f;
        for (int j = 0; j < NROW; ++j) s += g_h[(size_t)j * NCP + col];
        v = s * (1.0f / (float)NROW);
    }
    out[idx] = fmaxf(v, 0.f);
}

// ---------------- launcher ----------------
extern "C" void kernel_launch(void* const* d_in, const int* in_sizes, int n_in,
                              void* d_out, int out_size)
{
    (void)in_sizes; (void)n_in; (void)out_size;
    const float* X    = (const float*)d_in[0];
    const float* Amat = (const float*)d_in[1];
    const float* W    = (const float*)d_in[2];
    const float* avec = (const float*)d_in[3];
    float* out = (float*)d_out;

    cudaFuncSetAttribute(k_gemm1, cudaFuncAttributeMaxDynamicSharedMemorySize, 3 * G1_STAGE);
    cudaFuncSetAttribute(k_gemm2, cudaFuncAttributeMaxDynamicSharedMemorySize, 3 * G2_STAGE);

    __nv_bfloat16 *pXcat, *pWcat;
    char *pAq, *pBq;
    float *ph, *pout2, *pS;
    cudaGetSymbolAddress((void**)&pXcat, gXcat);
    cudaGetSymbolAddress((void**)&pWcat, gWcat);
    cudaGetSymbolAddress((void**)&pAq,   gAq);
    cudaGetSymbolAddress((void**)&pBq,   gBq);
    cudaGetSymbolAddress((void**)&ph,    g_h);
    cudaGetSymbolAddress((void**)&pout2, g_out2);
    cudaGetSymbolAddress((void**)&pS,    g_s);

    // prep / conversion
    k_convA<<<(NROW * NROW) / (256 * 16), 256>>>(Amat);
    k_prepX<<<(NROW * FDIM) / 256, 256>>>(X);
    k_prepW<<<(FDIM * CC) / 256, 256>>>(W);

    // GEMM1: h = Xcat @ Wcat^T   (M=4096, N=576pad, K=768, exact bf16 hi/lo)
    k_gemm1<<<dim3(NCP / 64, NROW / 128), 256, 3 * G1_STAGE>>>(
        pXcat, KCAT, pWcat, KCAT, ph, NCP, KCAT / 64);

    // weights + weighted features, column scales, transpose+quantize
    k_edst<<<NROW, 256>>>(avec);
    k_colmax1<<<16, 256>>>();
    k_colmax2<<<1, 576>>>();
    k_trans<<<dim3(18, 128), 256>>>();

    // GEMM2: Out2 = A @ Hw via 3 fused s8 digit planes (K=4096, BK=128)
    k_gemm2<<<dim3(NCP / 64, NROW / 128), 512, 3 * G2_STAGE>>>(
        pAq, pBq, pS, pout2, NROW / 128);

    // divide + permute + relu
    k_epilogue<<<(NROW * CC) / 256, 256>>>(out);
}

// round 13
// speedup vs baseline: 3.0775x; 3.0775x over previous
#include <cuda_runtime.h>
#include <cuda_bf16.h>
#include <cstdint>
#include <math.h>

// ---------------- problem constants ----------------
#define NROW   4096
#define FDIM   256
#define HH     8
#define UU     64
#define CC     512      // U*H
#define NCREAL 520      // CC + HH
#define NCP    576      // padded to 9 tiles of 64
#define KX     512      // K for GEMM1 DUAL: [Xhi|Xlo]

// ---------------- device scratch (no allocs) ----------------
__device__ __nv_bfloat16  gA    [NROW * NROW];   // bf16 adjacency (exact 0/1)
__device__ __nv_bfloat16  gXcat [NROW * KX];     // [Xhi|Xlo]
__device__ __nv_bfloat16  gW0   [NCP  * KX];     // row c: [Whi|Whi]; rows 512..575 stay 0
__device__ __nv_bfloat16  gW1   [NCP  * KX];     // row c: [Wlo|Wlo]; rows 512..575 stay 0
__device__ float          g_h   [NROW * NCP];    // X@W (cols 512..575 = 0)
__device__ float          g_hw  [NROW * NCREAL]; // [w*h (512) | w (8)] fp32
__device__ __nv_bfloat16  gBthi [NCP  * NROW];   // Hw^T hi (rows 520..575 stay 0)
__device__ __nv_bfloat16  gBtlo [NCP  * NROW];   // Hw^T lo
__device__ float          g_out2[NROW * NCP];    // A@Hw

// ---------------- helpers ----------------
__device__ __forceinline__ uint32_t smem_to_u32(const void* p) {
    uint32_t a;
    asm("{ .reg .u64 t; cvta.to.shared.u64 t, %1; cvt.u32.u64 %0, t; }" : "=r"(a) : "l"(p));
    return a;
}

#define LDSM_X4(r, addr) \
    asm volatile("ldmatrix.sync.aligned.m8n8.x4.shared.b16 {%0,%1,%2,%3}, [%4];" \
        : "=r"((r)[0]), "=r"((r)[1]), "=r"((r)[2]), "=r"((r)[3]) : "r"(addr))

__device__ __forceinline__ void mma16816(float* d, const uint32_t* a,
                                         uint32_t b0, uint32_t b1) {
    asm volatile(
        "mma.sync.aligned.m16n8k16.row.col.f32.bf16.bf16.f32 "
        "{%0,%1,%2,%3}, {%4,%5,%6,%7}, {%8,%9}, {%0,%1,%2,%3};"
        : "+f"(d[0]), "+f"(d[1]), "+f"(d[2]), "+f"(d[3])
        : "r"(a[0]), "r"(a[1]), "r"(a[2]), "r"(a[3]), "r"(b0), "r"(b1));
}

// ---------------------------------------------------------------------------
// DUAL GEMM: C = A @ B0t^T + A @ B1t^T (fused per K-chunk).
// Tile 128x64, BK=64, 128 threads (4 warps 2x2, warp tile 64x32),
// 3-stage cp.async, XOR-16B swizzle, fragment double-buffering. (R9-proven)
// Used for BOTH GEMM1 ([Xhi|Xlo] @ {[Whi|Whi],[Wlo|Wlo]}, K=512)
// and GEMM2 (A @ {Bthi,Btlo}, K=4096).
// ---------------------------------------------------------------------------
#define G2_STAGE 32768
#define G2_OFFB0 16384
#define G2_OFFB1 24576

__global__ __launch_bounds__(128, 2) void k_gemm_dual(
    const __nv_bfloat16* __restrict__ A, int lda,
    const __nv_bfloat16* __restrict__ B0, const __nv_bfloat16* __restrict__ B1, int ldb,
    float* __restrict__ C, int ldc, int T)
{
    extern __shared__ char smem[];
    const uint32_t sb = smem_to_u32(smem);
    const int tid = threadIdx.x, lane = tid & 31, wid = tid >> 5;
    const int warp_m = wid & 1, warp_n = wid >> 1;
    const int m0 = blockIdx.y * 128, n0 = blockIdx.x * 64;

    auto issue_stage = [&](int t) {
        const uint32_t so = sb + (t % 3) * G2_STAGE;
        const __nv_bfloat16* Ak = A + (size_t)m0 * lda + t * 64;
#pragma unroll
        for (int i = 0; i < 8; i++) {
            const int idx = tid + (i << 7), r = idx >> 3, c = idx & 7;
            const void* src = Ak + (size_t)r * lda + c * 8;
            const uint32_t dst = so + r * 128 + ((c ^ (r & 7)) << 4);
            asm volatile("cp.async.cg.shared.global [%0], [%1], 16;" :: "r"(dst), "l"(src));
        }
        const __nv_bfloat16* Bk0 = B0 + (size_t)n0 * ldb + t * 64;
#pragma unroll
        for (int i = 0; i < 4; i++) {
            const int idx = tid + (i << 7), r = idx >> 3, c = idx & 7;
            const void* src = Bk0 + (size_t)r * ldb + c * 8;
            const uint32_t dst = so + G2_OFFB0 + r * 128 + ((c ^ (r & 7)) << 4);
            asm volatile("cp.async.cg.shared.global [%0], [%1], 16;" :: "r"(dst), "l"(src));
        }
        const __nv_bfloat16* Bk1 = B1 + (size_t)n0 * ldb + t * 64;
#pragma unroll
        for (int i = 0; i < 4; i++) {
            const int idx = tid + (i << 7), r = idx >> 3, c = idx & 7;
            const void* src = Bk1 + (size_t)r * ldb + c * 8;
            const uint32_t dst = so + G2_OFFB1 + r * 128 + ((c ^ (r & 7)) << 4);
            asm volatile("cp.async.cg.shared.global [%0], [%1], 16;" :: "r"(dst), "l"(src));
        }
        asm volatile("cp.async.commit_group;" ::: "memory");
    };

    float acc[4][4][4];
#pragma unroll
    for (int i = 0; i < 4; i++)
#pragma unroll
        for (int n = 0; n < 4; n++)
#pragma unroll
            for (int q = 0; q < 4; q++) acc[i][n][q] = 0.f;

    issue_stage(0);
    issue_stage(1);

    const int rA = warp_m * 64 + (lane & 15);
    const int rB = warp_n * 32 + (lane & 15);
    const int h  = lane >> 4;
    const int xa = rA & 7, xb = rB & 7;

    for (int t = 0; t < T; ++t) {
        asm volatile("cp.async.wait_group 1;" ::: "memory");
        __syncthreads();
        const uint32_t so = sb + (t % 3) * G2_STAGE;
        const uint32_t aAddr0 = so + rA * 128;
        const uint32_t bAddr0 = so + G2_OFFB0 + rB * 128;
        const uint32_t bAddr1 = so + G2_OFFB1 + rB * 128;

        uint32_t a[2][4][4], b0[2][2][4], b1[2][2][4];
        // preload ks=0
        {
            const int ch = h;
#pragma unroll
            for (int i = 0; i < 4; ++i)
                LDSM_X4(a[0][i], aAddr0 + i * 2048 + ((ch ^ xa) << 4));
#pragma unroll
            for (int j = 0; j < 2; ++j)
                LDSM_X4(b0[0][j], bAddr0 + j * 2048 + ((ch ^ xb) << 4));
#pragma unroll
            for (int j = 0; j < 2; ++j)
                LDSM_X4(b1[0][j], bAddr1 + j * 2048 + ((ch ^ xb) << 4));
        }
#pragma unroll
        for (int ks = 0; ks < 4; ++ks) {
            const int cur = ks & 1, nxt = cur ^ 1;
            if (ks < 3) {
                const int ch = 2 * (ks + 1) + h;
#pragma unroll
                for (int i = 0; i < 4; ++i)
                    LDSM_X4(a[nxt][i], aAddr0 + i * 2048 + ((ch ^ xa) << 4));
#pragma unroll
                for (int j = 0; j < 2; ++j)
                    LDSM_X4(b0[nxt][j], bAddr0 + j * 2048 + ((ch ^ xb) << 4));
#pragma unroll
                for (int j = 0; j < 2; ++j)
                    LDSM_X4(b1[nxt][j], bAddr1 + j * 2048 + ((ch ^ xb) << 4));
            }
#pragma unroll
            for (int i = 0; i < 4; ++i)
#pragma unroll
                for (int n = 0; n < 4; ++n)
                    mma16816(acc[i][n], a[cur][i], b0[cur][n >> 1][n & 1], b0[cur][n >> 1][(n & 1) + 2]);
#pragma unroll
            for (int i = 0; i < 4; ++i)
#pragma unroll
                for (int n = 0; n < 4; ++n)
                    mma16816(acc[i][n], a[cur][i], b1[cur][n >> 1][n & 1], b1[cur][n >> 1][(n & 1) + 2]);
        }
        if (t + 2 < T) issue_stage(t + 2);
    }

    const int gid = lane >> 2, tig = lane & 3;
#pragma unroll
    for (int i = 0; i < 4; ++i) {
        const int row = m0 + warp_m * 64 + i * 16 + gid;
#pragma unroll
        for (int n = 0; n < 4; ++n) {
            const int col = n0 + warp_n * 32 + n * 8 + tig * 2;
            float* Cp = C + (size_t)row * ldc + col;
            *(float2*)Cp = make_float2(acc[i][n][0], acc[i][n][1]);
            *(float2*)(Cp + (size_t)8 * ldc) = make_float2(acc[i][n][2], acc[i][n][3]);
        }
    }
}

// ---------------- small prep kernels ----------------
__global__ __launch_bounds__(256) void k_convA(const float* __restrict__ A)
{
    const size_t idx = (size_t)blockIdx.x * 256 + threadIdx.x;   // 8 elems each
    float4 a = ((const float4*)A)[idx * 2];
    float4 b = ((const float4*)A)[idx * 2 + 1];
    __nv_bfloat162 p0 = __float22bfloat162_rn(make_float2(a.x, a.y));
    __nv_bfloat162 p1 = __float22bfloat162_rn(make_float2(a.z, a.w));
    __nv_bfloat162 p2 = __float22bfloat162_rn(make_float2(b.x, b.y));
    __nv_bfloat162 p3 = __float22bfloat162_rn(make_float2(b.z, b.w));
    uint4 o;
    o.x = *(uint32_t*)&p0; o.y = *(uint32_t*)&p1; o.z = *(uint32_t*)&p2; o.w = *(uint32_t*)&p3;
    ((uint4*)gA)[idx] = o;
}

__global__ __launch_bounds__(256) void k_prepX(const float* __restrict__ X)
{
    const int idx = blockIdx.x * 256 + threadIdx.x;   // 1M
    const int i = idx >> 8, k = idx & 255;
    const float v = X[idx];
    __nv_bfloat16 hi = __float2bfloat16_rn(v);
    __nv_bfloat16 lo = __float2bfloat16_rn(v - __bfloat162float(hi));
    gXcat[i * KX + k]       = hi;
    gXcat[i * KX + 256 + k] = lo;
}

__global__ __launch_bounds__(256) void k_prepW(const float* __restrict__ W)
{
    const int idx = blockIdx.x * 256 + threadIdx.x;   // 131072
    const int k = idx >> 9, c = idx & 511;
    const float v = W[idx];
    __nv_bfloat16 hi = __float2bfloat16_rn(v);
    __nv_bfloat16 lo = __float2bfloat16_rn(v - __bfloat162float(hi));
    gW0[c * KX + k]       = hi;
    gW0[c * KX + 256 + k] = hi;
    gW1[c * KX + k]       = lo;
    gW1[c * KX + 256 + k] = lo;
}

// w = exp(h . a_dst); write [w*h | w] row-major fp32
__global__ __launch_bounds__(256) void k_edst(const float* __restrict__ avec)
{
    const int j = blockIdx.x, warp = threadIdx.x >> 5, lane = threadIdx.x & 31;
    const float* hrow = g_h + (size_t)j * NCP + warp * UU;
    const float h0 = hrow[lane], h1 = hrow[lane + 32];
    float p = h0 * avec[UU + lane] + h1 * avec[UU + 32 + lane];
#pragma unroll
    for (int o = 16; o > 0; o >>= 1) p += __shfl_xor_sync(0xffffffffu, p, o);
    const float wv = expf(p);
    float* dst = g_hw + (size_t)j * NCREAL + warp * UU;
    dst[lane]      = wv * h0;
    dst[lane + 32] = wv * h1;
    if (lane == 0) g_hw[(size_t)j * NCREAL + CC + warp] = wv;
}

// transpose g_hw[4096,520] -> gBthi/gBtlo[(576),4096] with hi/lo split
__global__ __launch_bounds__(256) void k_trans()
{
    __shared__ float tile[32][33];
    const int c0 = blockIdx.x * 32, j0 = blockIdx.y * 32;
    const int tid = threadIdx.x;
#pragma unroll
    for (int ph = 0; ph < 4; ++ph) {
        int idx = ph * 256 + tid, jr = idx >> 5, cc = idx & 31;
        int c = c0 + cc;
        tile[jr][cc] = (c < NCREAL) ? g_hw[(size_t)(j0 + jr) * NCREAL + c] : 0.f;
    }
    __syncthreads();
#pragma unroll
    for (int ph = 0; ph < 4; ++ph) {
        int idx = ph * 256 + tid, cr = idx >> 5, jc = idx & 31;
        int c = c0 + cr;
        if (c < NCREAL) {
            float v = tile[jc][cr];
            __nv_bfloat16 hi = __float2bfloat16_rn(v);
            __nv_bfloat16 lo = __float2bfloat16_rn(v - __bfloat162float(hi));
            gBthi[(size_t)c * NROW + j0 + jc] = hi;
            gBtlo[(size_t)c * NROW + j0 + jc] = lo;
        }
    }
}

// out[i, u*8+h] = relu( num/den ); fully-masked-row fallback computed on demand
__global__ __launch_bounds__(256) void k_epilogue(float* __restrict__ out)
{
    const int idx = blockIdx.x * 256 + threadIdx.x;
    const int i = idx >> 9, o = idx & 511;
    const int head = o & 7, u = o >> 3;
    const int col = head * UU + u;
    const float den = g_out2[(size_t)i * NCP + CC + head];
    float v;
    if (den > 0.f) {
        v = g_out2[(size_t)i * NCP + col] / den;
    } else {
        // reference softmax over an all-masked row degenerates to uniform 1/N
        float s = 0.f;
        for (int j = 0; j < NROW; ++j) s += g_h[(size_t)j * NCP + col];
        v = s * (1.0f / (float)NROW);
    }
    out[idx] = fmaxf(v, 0.f);
}

// ---------------- launcher ----------------
extern "C" void kernel_launch(void* const* d_in, const int* in_sizes, int n_in,
                              void* d_out, int out_size)
{
    (void)in_sizes; (void)n_in; (void)out_size;
    const float* X    = (const float*)d_in[0];
    const float* Amat = (const float*)d_in[1];
    const float* W    = (const float*)d_in[2];
    const float* avec = (const float*)d_in[3];
    float* out = (float*)d_out;

    cudaFuncSetAttribute(k_gemm_dual, cudaFuncAttributeMaxDynamicSharedMemorySize, 3 * G2_STAGE);

    __nv_bfloat16 *pXcat, *pW0, *pW1, *pA, *pBthi, *pBtlo;
    float *ph, *pout2;
    cudaGetSymbolAddress((void**)&pXcat, gXcat);
    cudaGetSymbolAddress((void**)&pW0,   gW0);
    cudaGetSymbolAddress((void**)&pW1,   gW1);
    cudaGetSymbolAddress((void**)&pA,    gA);
    cudaGetSymbolAddress((void**)&pBthi, gBthi);
    cudaGetSymbolAddress((void**)&pBtlo, gBtlo);
    cudaGetSymbolAddress((void**)&ph,    g_h);
    cudaGetSymbolAddress((void**)&pout2, g_out2);

    // prep / conversion
    k_convA<<<(NROW * NROW) / (256 * 8), 256>>>(Amat);
    k_prepX<<<(NROW * FDIM) / 256, 256>>>(X);
    k_prepW<<<(FDIM * CC) / 256, 256>>>(W);

    // GEMM1 (DUAL, fully exact): h = [Xhi|Xlo] @ ([Whi|Whi]^T + [Wlo|Wlo]^T)
    //   = Xhi@Whi + Xlo@Whi + Xhi@Wlo + Xlo@Wlo    (M=4096, N=576pad, K=512)
    k_gemm_dual<<<dim3(NCP / 64, NROW / 128), 128, 3 * G2_STAGE>>>(
        pXcat, KX, pW0, pW1, KX, ph, NCP, KX / 64);

    // weights + weighted features, transpose+split
    k_edst<<<NROW, 256>>>(avec);
    k_trans<<<dim3(18, 128), 256>>>();

    // GEMM2 (DUAL): Out2 = A @ (Hw_hi + Hw_lo)   (K=4096)
    k_gemm_dual<<<dim3(NCP / 64, NROW / 128), 128, 3 * G2_STAGE>>>(
        pA, NROW, pBthi, pBtlo, NROW, pout2, NCP, NROW / 64);

    // divide + permute + relu
    k_epilogue<<<(NROW * CC) / 256, 256>>>(out);
}